// round 12
// baseline (speedup 1.0000x reference)
#include <cuda_runtime.h>
#include <cuda_bf16.h>
#include <cstdint>

#define Bb 4
#define Hh 16
#define Ll 8192
#define Dd 64
#define BH (Bb*Hh)
#define SCALE 0.10511205190671431f   // 8192^(-1/4)
#define NCHUNK 16
#define RPC (Ll/NCHUNK)              // 512 rows per chunk
#define NTILE (RPC/64)               // 8 tiles of 64 rows
#define PAD 72                       // bf16 row stride (144B, conflict-free)

// __device__ scratch (allocation-free rule)
__device__ float g_scratch[(size_t)NCHUNK*BH*Dd*Dd];          // 16.7 MB fp32 partial KV
__device__ __nv_bfloat16 g_KVhi[(size_t)BH*Dd*Dd];            // 0.5 MB
__device__ __nv_bfloat16 g_KVlo[(size_t)BH*Dd*Dd];            // 0.5 MB

// ---------------- helpers ----------------
__device__ __forceinline__ uint32_t s2u(const void* p) {
    uint32_t a;
    asm("{ .reg .u64 t; cvta.to.shared.u64 t, %1; cvt.u32.u64 %0, t; }" : "=r"(a) : "l"(p));
    return a;
}
__device__ __forceinline__ void cp16(uint32_t dst, const void* src) {
    asm volatile("cp.async.cg.shared.global [%0], [%1], 16;" :: "r"(dst), "l"(src) : "memory");
}
#define CPCOMMIT() asm volatile("cp.async.commit_group;" ::: "memory")
#define CPWAIT(n)  asm volatile("cp.async.wait_group %0;" :: "n"(n) : "memory")
#define BAR_SYNC(id)   asm volatile("bar.sync %0, 256;"   :: "r"(id) : "memory")
#define BAR_ARRIVE(id) asm volatile("bar.arrive %0, 256;" :: "r"(id) : "memory")
__device__ __forceinline__ void ldsm4t(uint32_t addr, uint32_t* r) {
    asm volatile("ldmatrix.sync.aligned.m8n8.x4.trans.shared.b16 {%0,%1,%2,%3}, [%4];"
                 : "=r"(r[0]), "=r"(r[1]), "=r"(r[2]), "=r"(r[3]) : "r"(addr));
}
__device__ __forceinline__ void ldsm4(uint32_t addr, uint32_t* r) {
    asm volatile("ldmatrix.sync.aligned.m8n8.x4.shared.b16 {%0,%1,%2,%3}, [%4];"
                 : "=r"(r[0]), "=r"(r[1]), "=r"(r[2]), "=r"(r[3]) : "r"(addr));
}
__device__ __forceinline__ void mma16816(float* c, const uint32_t* a, uint32_t b0, uint32_t b1) {
    asm volatile("mma.sync.aligned.m16n8k16.row.col.f32.bf16.bf16.f32 "
                 "{%0,%1,%2,%3},{%4,%5,%6,%7},{%8,%9},{%0,%1,%2,%3};"
                 : "+f"(c[0]), "+f"(c[1]), "+f"(c[2]), "+f"(c[3])
                 : "r"(a[0]), "r"(a[1]), "r"(a[2]), "r"(a[3]), "r"(b0), "r"(b1));
}
__device__ __forceinline__ float elu_p1(float x) { float e = __expf(x); return x > 0.0f ? x + 1.0f : e; }
__device__ __forceinline__ uint32_t cvt2(float a, float b) {
    uint32_t r;
    asm("cvt.rn.bf16x2.f32 %0, %1, %2;" : "=r"(r) : "f"(b), "f"(a));
    return r;
}
__device__ __forceinline__ float bflo(uint32_t u) { return __uint_as_float(u << 16); }
__device__ __forceinline__ float bfhi(uint32_t u) { return __uint_as_float(u & 0xffff0000u); }
__device__ __forceinline__ void split4(float f0, float f1, float f2, float f3,
                                       uint2& hi, uint2& lo) {
    hi.x = cvt2(f0, f1);  hi.y = cvt2(f2, f3);
    lo.x = cvt2(f0 - bflo(hi.x), f1 - bfhi(hi.x));
    lo.y = cvt2(f2 - bflo(hi.y), f3 - bfhi(hi.y));
}

// phase1 dyn smem: 2 buffers x (khi,klo,vhi,vlo) of 64*PAD bf16
#define T_KHI 0
#define T_KLO 9216
#define T_VHI 18432
#define T_VLO 27648
#define P1_BUF 36864
#define P1_SZ  (2*P1_BUF)     // 73728
// phase2 dynamic smem layout (R8)
#define P2_STQ 0
#define P2_QHI 32768
#define P2_QLO 41984
#define P2_KVH 51200
#define P2_KVL 60416
#define P2_SZ  69632

// ============================================================
// Phase 1 (warp-specialized): partial KV[d][e] = sum_l Kf[l][d]*Vm[l][e]
// grid (NCHUNK, BH), 256 thr: warps 0-3 consumers (MMA), 4-7 producers.
// Named-barrier pipeline: FULL ids {0,1}, EMPTY ids {2,3}, double-buffered.
// ============================================================
__global__ void __launch_bounds__(256)
phase1_kernel(const float* __restrict__ Kp, const float* __restrict__ Vp,
              const float* __restrict__ maskp, const float* __restrict__ pip,
              const float* __restrict__ mup) {
    extern __shared__ char smem[];
    const uint32_t sb = s2u(smem);
    const int t = threadIdx.x, lane = t & 31, w = t >> 5;
    const int chunk = blockIdx.x, bhidx = blockIdx.y, b = bhidx / Hh, h = bhidx % Hh;

    const size_t base = ((size_t)bhidx*Ll + (size_t)chunk*RPC) * 64;

    if (w >= 4) {
        // ---------------- PRODUCER (warps 4-7, 128 threads) ----------------
        const int pt = t - 128;
        const int dq = (pt & 15) * 4;      // constant across j (128 % 16 == 0)
        const int row0 = pt >> 4;          // rows row0 + 8*j
        const float p0 = fminf(fmaxf(pip[0], 0.f), 1.f);
        const float p1 = fminf(fmaxf(pip[1], 0.f), 1.f);
        const float ps = p0 + p1;
        float mus4[4];
#pragma unroll
        for (int c = 0; c < 4; c++)
            mus4[c] = p0 * mup[h*64 + dq + c] + p1 * mup[(Hh + h)*64 + dq + c];

        const float* __restrict__ Kb = Kp + base;
        const float* __restrict__ Vb = Vp + base;
        const float* __restrict__ mb = maskp + (size_t)b*Ll + (size_t)chunk*RPC;

        float4 kreg[8], vreg[8];
        float  mreg[8];

#define LOADP(tl) do { const int _l0 = (tl) * 64; \
    _Pragma("unroll") \
    for (int j = 0; j < 8; j++) { \
        const int row = row0 + 8*j; \
        const size_t off = (size_t)(_l0 + row)*64 + dq; \
        kreg[j] = *(const float4*)(Kb + off); \
        vreg[j] = *(const float4*)(Vb + off); \
        mreg[j] = mb[_l0 + row]; \
    } } while (0)

        LOADP(0);
        for (int tile = 0; tile < NTILE; tile++) {
            const int bf = tile & 1;
            if (tile >= 2) BAR_SYNC(2 + bf);            // consumers done with buffer
            char* bp = smem + bf * P1_BUF;
            __nv_bfloat16* khi = (__nv_bfloat16*)(bp + T_KHI);
            __nv_bfloat16* klo = (__nv_bfloat16*)(bp + T_KLO);
            __nv_bfloat16* vhi = (__nv_bfloat16*)(bp + T_VHI);
            __nv_bfloat16* vlo = (__nv_bfloat16*)(bp + T_VLO);
#pragma unroll
            for (int j = 0; j < 8; j++) {
                const int row = row0 + 8*j;
                const float m = mreg[j], msc = m * SCALE;
                float f0 = elu_p1(kreg[j].x*ps - mus4[0]) * msc;
                float f1 = elu_p1(kreg[j].y*ps - mus4[1]) * msc;
                float f2 = elu_p1(kreg[j].z*ps - mus4[2]) * msc;
                float f3 = elu_p1(kreg[j].w*ps - mus4[3]) * msc;
                uint2 kh, kl2; split4(f0, f1, f2, f3, kh, kl2);
                *(uint2*)&khi[row*PAD + dq] = kh;
                *(uint2*)&klo[row*PAD + dq] = kl2;
                float g0 = vreg[j].x * m, g1 = vreg[j].y * m;
                float g2 = vreg[j].z * m, g3 = vreg[j].w * m;
                uint2 vh, vl; split4(g0, g1, g2, g3, vh, vl);
                *(uint2*)&vhi[row*PAD + dq] = vh;
                *(uint2*)&vlo[row*PAD + dq] = vl;
            }
            if (tile + 1 < NTILE) LOADP(tile + 1);      // LDGs fly under consumer MMA
            BAR_ARRIVE(bf);                              // buffer full
        }
#undef LOADP
    } else {
        // ---------------- CONSUMER (warps 0-3, 128 threads) ----------------
        const int md = w * 16;
        const int gr = lane >> 3, r8 = lane & 7;
        const uint32_t aoff = ((uint32_t)((((gr & 2) ? 8 : 0) + r8) * PAD + md + ((gr & 1) ? 8 : 0))) * 2;
        const uint32_t boff = ((uint32_t)((((gr & 1) ? 8 : 0) + r8) * PAD + ((gr & 2) ? 8 : 0))) * 2;

        float acc[8][4];
#pragma unroll
        for (int i = 0; i < 8; i++)
#pragma unroll
            for (int j = 0; j < 4; j++) acc[i][j] = 0.f;

        for (int tile = 0; tile < NTILE; tile++) {
            const int bf = tile & 1;
            BAR_SYNC(bf);                                // buffer full
            const uint32_t bufb = sb + (uint32_t)(bf * P1_BUF);
            const uint32_t skh = bufb + T_KHI, skl = bufb + T_KLO;
            const uint32_t svh = bufb + T_VHI, svl = bufb + T_VLO;
#pragma unroll
            for (int kl = 0; kl < 64; kl += 16) {
                const uint32_t kadd = (uint32_t)(kl * PAD * 2);
                uint32_t ah[4], al[4];
                ldsm4t(skh + kadd + aoff, ah);
                ldsm4t(skl + kadd + aoff, al);
#pragma unroll
                for (int p = 0; p < 4; p++) {
                    const uint32_t badd = kadd + (uint32_t)(p * 32);
                    uint32_t vh[4], vl[4];
                    ldsm4t(svh + badd + boff, vh);
                    ldsm4t(svl + badd + boff, vl);
                    mma16816(acc[2*p], ah, vh[0], vh[1]);
                    mma16816(acc[2*p], ah, vl[0], vl[1]);
                    mma16816(acc[2*p], al, vh[0], vh[1]);
                    mma16816(acc[2*p+1], ah, vh[2], vh[3]);
                    mma16816(acc[2*p+1], ah, vl[2], vl[3]);
                    mma16816(acc[2*p+1], al, vh[2], vh[3]);
                }
            }
            BAR_ARRIVE(2 + bf);                          // buffer empty
        }

        float* outp = g_scratch + ((size_t)chunk*BH + bhidx) * 4096;
        const int rw = lane >> 2, cq = (lane & 3) * 2;
#pragma unroll
        for (int j = 0; j < 8; j++) {
            float2 lo = { acc[j][0], acc[j][1] };
            float2 hi = { acc[j][2], acc[j][3] };
            *(float2*)&outp[(md + rw) * 64 + 8*j + cq]     = lo;
            *(float2*)&outp[(md + 8 + rw) * 64 + 8*j + cq] = hi;
        }
    }
}

// ============================================================
// Reduce: KV = sum over 16 chunks; emit bf16 hi/lo. grid (BH, 4), 256 thr.
// ============================================================
__global__ void __launch_bounds__(256)
reduce_kernel() {
    const int bhidx = blockIdx.x, part = blockIdx.y, t = threadIdx.x;
    const int pos = part*1024 + t*4;
    float4 s = make_float4(0.f, 0.f, 0.f, 0.f);
#pragma unroll
    for (int c = 0; c < NCHUNK; c++) {
        const float4 v = *(const float4*)(g_scratch + ((size_t)c*BH + bhidx)*4096 + pos);
        s.x += v.x; s.y += v.y; s.z += v.z; s.w += v.w;
    }
    uint2 hi, lo;
    split4(s.x, s.y, s.z, s.w, hi, lo);
    *(uint2*)(g_KVhi + (size_t)bhidx*4096 + pos) = hi;
    *(uint2*)(g_KVlo + (size_t)bhidx*4096 + pos) = lo;
}

// ============================================================
// Phase 2 (R8/R11): out[l][e] = sum_d Qf[l][d]*KV[d][e]
// grid (Ll/128, BH), 128 thr / 4 warps; cp.async Q staging, 3 CTAs/SM.
// ============================================================
__global__ void __launch_bounds__(128, 3)
phase2_kernel(const float* __restrict__ Qp, float* __restrict__ outp) {
    extern __shared__ char smem[];
    const uint32_t sb = s2u(smem);
    const int t = threadIdx.x, lane = t & 31, w = t >> 5;
    const int rb = blockIdx.x, bhidx = blockIdx.y;

    const float* __restrict__ Qb = Qp + ((size_t)bhidx*Ll + (size_t)rb*128) * 64;

#pragma unroll
    for (int st = 0; st < 2; st++) {
        const float* qs = Qb + st*4096;
        const uint32_t qd = sb + P2_STQ + st*16384;
#pragma unroll
        for (int j = 0; j < 8; j++) {
            const int u = t + 128*j;
            cp16(qd + u*16, qs + u*4);
        }
        CPCOMMIT();
    }

    __nv_bfloat16* kvh = (__nv_bfloat16*)(smem + P2_KVH);
    __nv_bfloat16* kvl = (__nv_bfloat16*)(smem + P2_KVL);
#pragma unroll
    for (int i = 0; i < 4; i++) {
        const int idx8 = t + 128*i;
        const int row = idx8 >> 3, cg = (idx8 & 7) * 8;
        *(uint4*)&kvh[row*PAD + cg] = *(const uint4*)(g_KVhi + (size_t)bhidx*4096 + row*64 + cg);
        *(uint4*)&kvl[row*PAD + cg] = *(const uint4*)(g_KVlo + (size_t)bhidx*4096 + row*64 + cg);
    }

    __nv_bfloat16* qhi = (__nv_bfloat16*)(smem + P2_QHI);
    __nv_bfloat16* qlo = (__nv_bfloat16*)(smem + P2_QLO);
    const int l0 = w * 16;
    const int gr = lane >> 3, r8 = lane & 7;
    const uint32_t aoff = ((uint32_t)((l0 + ((gr & 1) ? 8 : 0) + r8) * PAD + ((gr & 2) ? 8 : 0))) * 2;
    const uint32_t boff = ((uint32_t)((((gr & 1) ? 8 : 0) + r8) * PAD + ((gr & 2) ? 8 : 0))) * 2;
    const uint32_t sqh = sb + P2_QHI, sql = sb + P2_QLO, svh = sb + P2_KVH, svl = sb + P2_KVL;

#pragma unroll
    for (int bt = 0; bt < 2; bt++) {
        if (bt == 0) { CPWAIT(1); } else { CPWAIT(0); }
        __syncthreads();
        const float* stq = (const float*)(smem + P2_STQ + bt*16384);
#pragma unroll
        for (int j = 0; j < 8; j++) {
            const int u = t + 128*j, row = u >> 4, dq = (u & 15) * 4;
            const float4 q = *(const float4*)(stq + u*4);
            float f0 = elu_p1(q.x) * SCALE, f1 = elu_p1(q.y) * SCALE;
            float f2 = elu_p1(q.z) * SCALE, f3 = elu_p1(q.w) * SCALE;
            uint2 qh, ql;
            split4(f0, f1, f2, f3, qh, ql);
            *(uint2*)&qhi[row*PAD + dq] = qh;
            *(uint2*)&qlo[row*PAD + dq] = ql;
        }
        __syncthreads();

        float acc[8][4];
#pragma unroll
        for (int i = 0; i < 8; i++)
#pragma unroll
            for (int j = 0; j < 4; j++) acc[i][j] = 0.f;

#pragma unroll
        for (int kd = 0; kd < 64; kd += 16) {
            uint32_t ah[4], al[4];
            ldsm4(sqh + aoff + (uint32_t)(kd*2), ah);
            ldsm4(sql + aoff + (uint32_t)(kd*2), al);
#pragma unroll
            for (int p = 0; p < 4; p++) {
                const uint32_t badd = (uint32_t)(kd * PAD * 2 + p * 32);
                uint32_t vh[4], vl[4];
                ldsm4t(svh + badd + boff, vh);
                ldsm4t(svl + badd + boff, vl);
                mma16816(acc[2*p], ah, vh[0], vh[1]);
                mma16816(acc[2*p], ah, vl[0], vl[1]);
                mma16816(acc[2*p], al, vh[0], vh[1]);
                mma16816(acc[2*p+1], ah, vh[2], vh[3]);
                mma16816(acc[2*p+1], ah, vl[2], vl[3]);
                mma16816(acc[2*p+1], al, vh[2], vh[3]);
            }
        }

        float* __restrict__ ob = outp + ((size_t)bhidx*Ll + (size_t)rb*128 + (size_t)bt*64) * 64;
        const int rw = lane >> 2, cq = (lane & 3) * 2;
#pragma unroll
        for (int j = 0; j < 8; j++) {
            float2 lo = { acc[j][0], acc[j][1] };
            float2 hi = { acc[j][2], acc[j][3] };
            *(float2*)&ob[(l0 + rw) * 64 + 8*j + cq]     = lo;
            *(float2*)&ob[(l0 + 8 + rw) * 64 + 8*j + cq] = hi;
        }
    }
}

// ============================================================
// Launch
// ============================================================
extern "C" void kernel_launch(void* const* d_in, const int* in_sizes, int n_in,
                              void* d_out, int out_size) {
    const float* Q    = (const float*)d_in[0];
    const float* K    = (const float*)d_in[1];
    const float* V    = (const float*)d_in[2];
    const float* mask = (const float*)d_in[3];
    const float* pi   = (const float*)d_in[4];
    const float* mu   = (const float*)d_in[5];
    float* out = (float*)d_out;

    cudaFuncSetAttribute(phase1_kernel, cudaFuncAttributeMaxDynamicSharedMemorySize, P1_SZ);
    cudaFuncSetAttribute(phase2_kernel, cudaFuncAttributeMaxDynamicSharedMemorySize, P2_SZ);

    dim3 g1(NCHUNK, BH);
    phase1_kernel<<<g1, 256, P1_SZ>>>(K, V, mask, pi, mu);
    dim3 g2(BH, 4);
    reduce_kernel<<<g2, 256>>>();
    dim3 g3(Ll / 128, BH);
    phase2_kernel<<<g3, 128, P2_SZ>>>(Q, out);
}

// round 13
// speedup vs baseline: 1.0888x; 1.0888x over previous
#include <cuda_runtime.h>
#include <cuda_bf16.h>
#include <cstdint>

#define Bb 4
#define Hh 16
#define Ll 8192
#define Dd 64
#define BH (Bb*Hh)
#define SCALE 0.10511205190671431f   // 8192^(-1/4)
#define NCHUNK 16
#define RPC (Ll/NCHUNK)              // 512 rows per chunk
#define NTILE (RPC/64)               // 8 tiles of 64 rows
#define PAD 72                       // bf16 row stride (144B, conflict-free)
#define P2ROWS 256                   // rows per phase2 CTA
#define P2TILES (P2ROWS/64)          // 4

// __device__ scratch (allocation-free rule)
__device__ float g_scratch[(size_t)NCHUNK*BH*Dd*Dd];          // 16.7 MB fp32 partial KV
__device__ __nv_bfloat16 g_KVhi[(size_t)BH*Dd*Dd];            // 0.5 MB
__device__ __nv_bfloat16 g_KVlo[(size_t)BH*Dd*Dd];            // 0.5 MB

// ---------------- helpers ----------------
__device__ __forceinline__ uint32_t s2u(const void* p) {
    uint32_t a;
    asm("{ .reg .u64 t; cvta.to.shared.u64 t, %1; cvt.u32.u64 %0, t; }" : "=r"(a) : "l"(p));
    return a;
}
__device__ __forceinline__ void ldsm4t(uint32_t addr, uint32_t* r) {
    asm volatile("ldmatrix.sync.aligned.m8n8.x4.trans.shared.b16 {%0,%1,%2,%3}, [%4];"
                 : "=r"(r[0]), "=r"(r[1]), "=r"(r[2]), "=r"(r[3]) : "r"(addr));
}
__device__ __forceinline__ void ldsm4(uint32_t addr, uint32_t* r) {
    asm volatile("ldmatrix.sync.aligned.m8n8.x4.shared.b16 {%0,%1,%2,%3}, [%4];"
                 : "=r"(r[0]), "=r"(r[1]), "=r"(r[2]), "=r"(r[3]) : "r"(addr));
}
__device__ __forceinline__ void mma16816(float* c, const uint32_t* a, uint32_t b0, uint32_t b1) {
    asm volatile("mma.sync.aligned.m16n8k16.row.col.f32.bf16.bf16.f32 "
                 "{%0,%1,%2,%3},{%4,%5,%6,%7},{%8,%9},{%0,%1,%2,%3};"
                 : "+f"(c[0]), "+f"(c[1]), "+f"(c[2]), "+f"(c[3])
                 : "r"(a[0]), "r"(a[1]), "r"(a[2]), "r"(a[3]), "r"(b0), "r"(b1));
}
__device__ __forceinline__ float elu_p1(float x) { float e = __expf(x); return x > 0.0f ? x + 1.0f : e; }
__device__ __forceinline__ uint32_t cvt2(float a, float b) {
    uint32_t r;
    asm("cvt.rn.bf16x2.f32 %0, %1, %2;" : "=r"(r) : "f"(b), "f"(a));
    return r;
}
__device__ __forceinline__ float bflo(uint32_t u) { return __uint_as_float(u << 16); }
__device__ __forceinline__ float bfhi(uint32_t u) { return __uint_as_float(u & 0xffff0000u); }
__device__ __forceinline__ void split4(float f0, float f1, float f2, float f3,
                                       uint2& hi, uint2& lo) {
    hi.x = cvt2(f0, f1);  hi.y = cvt2(f2, f3);
    lo.x = cvt2(f0 - bflo(hi.x), f1 - bfhi(hi.x));
    lo.y = cvt2(f2 - bflo(hi.y), f3 - bfhi(hi.y));
}

// ============================================================
// Phase 1 (R10/R11, 61.2us measured): partial KV = Kf^T @ Vm
// grid (NCHUNK, BH), 256 thr / 8 warps, unrestricted regs.
// Per tile: sync -> TRANSFORM(regs) -> LDG(t+1) -> sync -> MMA
// ============================================================
__global__ void __launch_bounds__(256)
phase1_kernel(const float* __restrict__ Kp, const float* __restrict__ Vp,
              const float* __restrict__ maskp, const float* __restrict__ pip,
              const float* __restrict__ mup) {
    __shared__ __nv_bfloat16 khi[64*PAD], klo[64*PAD], vhi[64*PAD], vlo[64*PAD];
    __shared__ float mus[64];
    const int t = threadIdx.x, lane = t & 31, w = t >> 5;
    const int chunk = blockIdx.x, bhidx = blockIdx.y, b = bhidx / Hh, h = bhidx % Hh;

    const float p0 = fminf(fmaxf(pip[0], 0.f), 1.f);
    const float p1 = fminf(fmaxf(pip[1], 0.f), 1.f);
    const float ps = p0 + p1;
    if (t < 64) mus[t] = p0 * mup[h*64 + t] + p1 * mup[(Hh + h)*64 + t];

    const size_t base = ((size_t)bhidx*Ll + (size_t)chunk*RPC) * 64;
    const float* __restrict__ Kb = Kp + base;
    const float* __restrict__ Vb = Vp + base;
    const float* __restrict__ mb = maskp + (size_t)b*Ll + (size_t)chunk*RPC;

    const int md = (w & 3) * 16, ne = (w >> 2) * 32;
    const int gr = lane >> 3, r8 = lane & 7;
    const uint32_t aoff = ((uint32_t)((((gr & 2) ? 8 : 0) + r8) * PAD + md + ((gr & 1) ? 8 : 0))) * 2;
    const uint32_t boff = ((uint32_t)((((gr & 1) ? 8 : 0) + r8) * PAD + ne + ((gr & 2) ? 8 : 0))) * 2;
    const uint32_t skh = s2u(khi), skl = s2u(klo), svh = s2u(vhi), svl = s2u(vlo);

    float acc[4][4];
#pragma unroll
    for (int i = 0; i < 4; i++)
#pragma unroll
        for (int j = 0; j < 4; j++) acc[i][j] = 0.f;

    float4 kreg[4], vreg[4];
    float  mreg[4];
    const int trow = t >> 4, tdq = (t & 15) * 4;

#define LOAD_TILE(tl) do { const int _l0 = (tl) * 64; \
    _Pragma("unroll") \
    for (int j = 0; j < 4; j++) { \
        const size_t off = (size_t)(_l0 + trow + 16*j)*64 + tdq; \
        kreg[j] = *(const float4*)(Kb + off); \
        vreg[j] = *(const float4*)(Vb + off); \
        mreg[j] = mb[_l0 + trow + 16*j]; \
    } } while (0)

#define TRANSFORM() do { \
    _Pragma("unroll") \
    for (int j = 0; j < 4; j++) { \
        const int row = trow + 16*j; \
        const float m = mreg[j], msc = m * SCALE; \
        float f0 = elu_p1(kreg[j].x*ps - mus[tdq+0]) * msc; \
        float f1 = elu_p1(kreg[j].y*ps - mus[tdq+1]) * msc; \
        float f2 = elu_p1(kreg[j].z*ps - mus[tdq+2]) * msc; \
        float f3 = elu_p1(kreg[j].w*ps - mus[tdq+3]) * msc; \
        uint2 kh, kl2; split4(f0, f1, f2, f3, kh, kl2); \
        *(uint2*)&khi[row*PAD + tdq] = kh; \
        *(uint2*)&klo[row*PAD + tdq] = kl2; \
        float g0 = vreg[j].x * m, g1 = vreg[j].y * m; \
        float g2 = vreg[j].z * m, g3 = vreg[j].w * m; \
        uint2 vh, vl; split4(g0, g1, g2, g3, vh, vl); \
        *(uint2*)&vhi[row*PAD + tdq] = vh; \
        *(uint2*)&vlo[row*PAD + tdq] = vl; \
    } } while (0)

    LOAD_TILE(0);

    for (int tile = 0; tile < NTILE; tile++) {
        __syncthreads();                  // prev MMA done; mus visible on tile 0
        TRANSFORM();
        if (tile + 1 < NTILE) LOAD_TILE(tile + 1);
        __syncthreads();

#pragma unroll
        for (int kl = 0; kl < 64; kl += 16) {
            const uint32_t kadd = (uint32_t)(kl * PAD * 2);
            uint32_t ah[4], al[4];
            ldsm4t(skh + kadd + aoff, ah);
            ldsm4t(skl + kadd + aoff, al);
            uint32_t bh0[4], bl0[4], bh1[4], bl1[4];
            ldsm4t(svh + kadd + boff,      bh0);
            ldsm4t(svl + kadd + boff,      bl0);
            ldsm4t(svh + kadd + boff + 32, bh1);
            ldsm4t(svl + kadd + boff + 32, bl1);
            mma16816(acc[0], ah, bh0[0], bh0[1]);
            mma16816(acc[0], ah, bl0[0], bl0[1]);
            mma16816(acc[0], al, bh0[0], bh0[1]);
            mma16816(acc[1], ah, bh0[2], bh0[3]);
            mma16816(acc[1], ah, bl0[2], bl0[3]);
            mma16816(acc[1], al, bh0[2], bh0[3]);
            mma16816(acc[2], ah, bh1[0], bh1[1]);
            mma16816(acc[2], ah, bl1[0], bl1[1]);
            mma16816(acc[2], al, bh1[0], bh1[1]);
            mma16816(acc[3], ah, bh1[2], bh1[3]);
            mma16816(acc[3], ah, bl1[2], bl1[3]);
            mma16816(acc[3], al, bh1[2], bh1[3]);
        }
    }
#undef LOAD_TILE
#undef TRANSFORM

    float* outp = g_scratch + ((size_t)chunk*BH + bhidx) * 4096;
    const int rw = lane >> 2, cq = (lane & 3) * 2;
#pragma unroll
    for (int j = 0; j < 4; j++) {
        float2 lo = { acc[j][0], acc[j][1] };
        float2 hi = { acc[j][2], acc[j][3] };
        *(float2*)&outp[(md + rw) * 64 + ne + 8*j + cq]     = lo;
        *(float2*)&outp[(md + 8 + rw) * 64 + ne + 8*j + cq] = hi;
    }
}

// ============================================================
// Reduce: KV = sum over 16 chunks; emit bf16 hi/lo. grid (BH, 4), 256 thr.
// ============================================================
__global__ void __launch_bounds__(256)
reduce_kernel() {
    const int bhidx = blockIdx.x, part = blockIdx.y, t = threadIdx.x;
    const int pos = part*1024 + t*4;
    float4 s = make_float4(0.f, 0.f, 0.f, 0.f);
#pragma unroll
    for (int c = 0; c < NCHUNK; c++) {
        const float4 v = *(const float4*)(g_scratch + ((size_t)c*BH + bhidx)*4096 + pos);
        s.x += v.x; s.y += v.y; s.z += v.z; s.w += v.w;
    }
    uint2 hi, lo;
    split4(s.x, s.y, s.z, s.w, hi, lo);
    *(uint2*)(g_KVhi + (size_t)bhidx*4096 + pos) = hi;
    *(uint2*)(g_KVlo + (size_t)bhidx*4096 + pos) = lo;
}

// ============================================================
// Phase 2 (new): out[l][e] = sum_d Qf[l][d]*KV[d][e]
// grid (Ll/P2ROWS, BH) = (32, 64), 256 thr / 8 warps.
// Each CTA: load KV once, then 4 tiles of 64 Q rows:
//   sync -> TRANSQ(regs) -> LOADQ(t+1) -> sync -> MMA+STG
// Warp (w&3): rows 16-strip; (w>>2): 32-col half. Static 37 KB smem.
// ============================================================
__global__ void __launch_bounds__(256)
phase2_kernel(const float* __restrict__ Qp, float* __restrict__ outp) {
    __shared__ __nv_bfloat16 qhi[64*PAD], qlo[64*PAD], kvh[64*PAD], kvl[64*PAD];
    const int t = threadIdx.x, lane = t & 31, w = t >> 5;
    const int rb = blockIdx.x, bhidx = blockIdx.y;

    // KV tiles once per CTA (L2-resident source)
#pragma unroll
    for (int i = 0; i < 2; i++) {
        const int idx8 = t + 256*i;
        const int row = idx8 >> 3, cg = (idx8 & 7) * 8;
        *(uint4*)&kvh[row*PAD + cg] = *(const uint4*)(g_KVhi + (size_t)bhidx*4096 + row*64 + cg);
        *(uint4*)&kvl[row*PAD + cg] = *(const uint4*)(g_KVlo + (size_t)bhidx*4096 + row*64 + cg);
    }

    const float* __restrict__ Qb = Qp + ((size_t)bhidx*Ll + (size_t)rb*P2ROWS) * 64;
    float* __restrict__ Ob = outp + ((size_t)bhidx*Ll + (size_t)rb*P2ROWS) * 64;

    const int md = (w & 3) * 16, ne = (w >> 2) * 32;
    const int gr = lane >> 3, r8 = lane & 7;
    // a-frag: normal ldsm of Q [l][d]; rows md + ((gr&1)?8:0) + r8, k-col ((gr&2)?8:0)
    const uint32_t aoff = ((uint32_t)((md + ((gr & 1) ? 8 : 0) + r8) * PAD + ((gr & 2) ? 8 : 0))) * 2;
    // b-frag: trans ldsm of KV [d][e]; cols folded with ne
    const uint32_t boff = ((uint32_t)((((gr & 1) ? 8 : 0) + r8) * PAD + ne + ((gr & 2) ? 8 : 0))) * 2;
    const uint32_t sqh = s2u(qhi), sql = s2u(qlo), svh = s2u(kvh), svl = s2u(kvl);
    const int rw = lane >> 2, cq = (lane & 3) * 2;

    float4 qreg[4];
    const int trow = t >> 4, tdq = (t & 15) * 4;   // rows trow + 16*j

#define LOADQ(tl) do { const int _l0 = (tl) * 64; \
    _Pragma("unroll") \
    for (int j = 0; j < 4; j++) { \
        qreg[j] = *(const float4*)(Qb + (size_t)(_l0 + trow + 16*j)*64 + tdq); \
    } } while (0)

#define TRANSQ() do { \
    _Pragma("unroll") \
    for (int j = 0; j < 4; j++) { \
        const int row = trow + 16*j; \
        float f0 = elu_p1(qreg[j].x) * SCALE, f1 = elu_p1(qreg[j].y) * SCALE; \
        float f2 = elu_p1(qreg[j].z) * SCALE, f3 = elu_p1(qreg[j].w) * SCALE; \
        uint2 qh, ql; split4(f0, f1, f2, f3, qh, ql); \
        *(uint2*)&qhi[row*PAD + tdq] = qh; \
        *(uint2*)&qlo[row*PAD + tdq] = ql; \
    } } while (0)

    LOADQ(0);

    for (int tile = 0; tile < P2TILES; tile++) {
        __syncthreads();                  // prev MMA done reading qhi/qlo; KV visible on tile 0
        TRANSQ();
        if (tile + 1 < P2TILES) LOADQ(tile + 1);
        __syncthreads();

        float acc[4][4];
#pragma unroll
        for (int i = 0; i < 4; i++)
#pragma unroll
            for (int j = 0; j < 4; j++) acc[i][j] = 0.f;

#pragma unroll
        for (int kd = 0; kd < 64; kd += 16) {
            uint32_t ah[4], al[4];
            ldsm4(sqh + aoff + (uint32_t)(kd*2), ah);
            ldsm4(sql + aoff + (uint32_t)(kd*2), al);
#pragma unroll
            for (int p = 0; p < 2; p++) {
                const uint32_t badd = (uint32_t)(kd * PAD * 2 + p * 32);
                uint32_t vh[4], vl[4];
                ldsm4t(svh + badd + boff, vh);
                ldsm4t(svl + badd + boff, vl);
                mma16816(acc[2*p], ah, vh[0], vh[1]);
                mma16816(acc[2*p], ah, vl[0], vl[1]);
                mma16816(acc[2*p], al, vh[0], vh[1]);
                mma16816(acc[2*p+1], ah, vh[2], vh[3]);
                mma16816(acc[2*p+1], ah, vl[2], vl[3]);
                mma16816(acc[2*p+1], al, vh[2], vh[3]);
            }
        }

        float* __restrict__ ob = Ob + (size_t)tile*64*64;
#pragma unroll
        for (int j = 0; j < 4; j++) {
            float2 lo = { acc[j][0], acc[j][1] };
            float2 hi = { acc[j][2], acc[j][3] };
            *(float2*)&ob[(md + rw) * 64 + ne + 8*j + cq]     = lo;
            *(float2*)&ob[(md + 8 + rw) * 64 + ne + 8*j + cq] = hi;
        }
    }
#undef LOADQ
#undef TRANSQ
}

// ============================================================
// Launch
// ============================================================
extern "C" void kernel_launch(void* const* d_in, const int* in_sizes, int n_in,
                              void* d_out, int out_size) {
    const float* Q    = (const float*)d_in[0];
    const float* K    = (const float*)d_in[1];
    const float* V    = (const float*)d_in[2];
    const float* mask = (const float*)d_in[3];
    const float* pi   = (const float*)d_in[4];
    const float* mu   = (const float*)d_in[5];
    float* out = (float*)d_out;

    dim3 g1(NCHUNK, BH);
    phase1_kernel<<<g1, 256>>>(K, V, mask, pi, mu);
    dim3 g2(BH, 4);
    reduce_kernel<<<g2, 256>>>();
    dim3 g3(Ll / P2ROWS, BH);
    phase2_kernel<<<g3, 256>>>(Q, out);
}

// round 14
// speedup vs baseline: 1.2625x; 1.1595x over previous
#include <cuda_runtime.h>
#include <cuda_fp16.h>
#include <cstdint>

#define Bb 4
#define Hh 16
#define Ll 8192
#define Dd 64
#define BH (Bb*Hh)
#define SCALE 0.10511205190671431f   // 8192^(-1/4)
#define NCHUNK 16
#define RPC (Ll/NCHUNK)              // 512 rows per chunk
#define NTILE (RPC/64)               // 8 tiles of 64 rows
#define PAD 72                       // f16 row stride (144B, conflict-free)
#define P2ROWS 256                   // rows per phase2 CTA
#define P2TILES (P2ROWS/64)          // 4

// __device__ scratch (allocation-free rule)
__device__ float g_scratch[(size_t)NCHUNK*BH*Dd*Dd];   // 16.7 MB fp32 partial KV
__device__ __half g_KVh[(size_t)BH*Dd*Dd];             // 0.5 MB fp16 KV

// ---------------- helpers ----------------
__device__ __forceinline__ uint32_t s2u(const void* p) {
    uint32_t a;
    asm("{ .reg .u64 t; cvta.to.shared.u64 t, %1; cvt.u32.u64 %0, t; }" : "=r"(a) : "l"(p));
    return a;
}
__device__ __forceinline__ void ldsm4t(uint32_t addr, uint32_t* r) {
    asm volatile("ldmatrix.sync.aligned.m8n8.x4.trans.shared.b16 {%0,%1,%2,%3}, [%4];"
                 : "=r"(r[0]), "=r"(r[1]), "=r"(r[2]), "=r"(r[3]) : "r"(addr));
}
__device__ __forceinline__ void ldsm4(uint32_t addr, uint32_t* r) {
    asm volatile("ldmatrix.sync.aligned.m8n8.x4.shared.b16 {%0,%1,%2,%3}, [%4];"
                 : "=r"(r[0]), "=r"(r[1]), "=r"(r[2]), "=r"(r[3]) : "r"(addr));
}
// fp16 MMA, fp32 accumulate
__device__ __forceinline__ void mma16816(float* c, const uint32_t* a, uint32_t b0, uint32_t b1) {
    asm volatile("mma.sync.aligned.m16n8k16.row.col.f32.f16.f16.f32 "
                 "{%0,%1,%2,%3},{%4,%5,%6,%7},{%8,%9},{%0,%1,%2,%3};"
                 : "+f"(c[0]), "+f"(c[1]), "+f"(c[2]), "+f"(c[3])
                 : "r"(a[0]), "r"(a[1]), "r"(a[2]), "r"(a[3]), "r"(b0), "r"(b1));
}
__device__ __forceinline__ float elu_p1(float x) { float e = __expf(x); return x > 0.0f ? x + 1.0f : e; }
// pack (a -> lo half, b -> hi half) as fp16x2
__device__ __forceinline__ uint32_t pkh(float a, float b) {
    uint32_t r;
    asm("cvt.rn.f16x2.f32 %0, %1, %2;" : "=r"(r) : "f"(b), "f"(a));
    return r;
}

// ============================================================
// Phase 1: partial KV[d][e] = sum_l Kf[l][d]*Vm[l][e]  (fp16 single-pass)
// grid (NCHUNK, BH), 256 thr / 8 warps.
// Per tile: sync -> TRANSFORM(regs) -> LDG(t+1) -> sync -> MMA
// ============================================================
__global__ void __launch_bounds__(256)
phase1_kernel(const float* __restrict__ Kp, const float* __restrict__ Vp,
              const float* __restrict__ maskp, const float* __restrict__ pip,
              const float* __restrict__ mup) {
    __shared__ __half khs[64*PAD], vhs[64*PAD];
    __shared__ float mus[64];
    const int t = threadIdx.x, lane = t & 31, w = t >> 5;
    const int chunk = blockIdx.x, bhidx = blockIdx.y, b = bhidx / Hh, h = bhidx % Hh;

    const float p0 = fminf(fmaxf(pip[0], 0.f), 1.f);
    const float p1 = fminf(fmaxf(pip[1], 0.f), 1.f);
    const float ps = p0 + p1;
    if (t < 64) mus[t] = p0 * mup[h*64 + t] + p1 * mup[(Hh + h)*64 + t];

    const size_t base = ((size_t)bhidx*Ll + (size_t)chunk*RPC) * 64;
    const float* __restrict__ Kb = Kp + base;
    const float* __restrict__ Vb = Vp + base;
    const float* __restrict__ mb = maskp + (size_t)b*Ll + (size_t)chunk*RPC;

    const int md = (w & 3) * 16, ne = (w >> 2) * 32;
    const int gr = lane >> 3, r8 = lane & 7;
    const uint32_t aoff = ((uint32_t)((((gr & 2) ? 8 : 0) + r8) * PAD + md + ((gr & 1) ? 8 : 0))) * 2;
    const uint32_t boff = ((uint32_t)((((gr & 1) ? 8 : 0) + r8) * PAD + ne + ((gr & 2) ? 8 : 0))) * 2;
    const uint32_t skh = s2u(khs), svh = s2u(vhs);

    float acc[4][4];
#pragma unroll
    for (int i = 0; i < 4; i++)
#pragma unroll
        for (int j = 0; j < 4; j++) acc[i][j] = 0.f;

    float4 kreg[4], vreg[4];
    float  mreg[4];
    const int trow = t >> 4, tdq = (t & 15) * 4;

#define LOAD_TILE(tl) do { const int _l0 = (tl) * 64; \
    _Pragma("unroll") \
    for (int j = 0; j < 4; j++) { \
        const size_t off = (size_t)(_l0 + trow + 16*j)*64 + tdq; \
        kreg[j] = *(const float4*)(Kb + off); \
        vreg[j] = *(const float4*)(Vb + off); \
        mreg[j] = mb[_l0 + trow + 16*j]; \
    } } while (0)

#define TRANSFORM() do { \
    _Pragma("unroll") \
    for (int j = 0; j < 4; j++) { \
        const int row = trow + 16*j; \
        const float m = mreg[j], msc = m * SCALE; \
        float f0 = elu_p1(kreg[j].x*ps - mus[tdq+0]) * msc; \
        float f1 = elu_p1(kreg[j].y*ps - mus[tdq+1]) * msc; \
        float f2 = elu_p1(kreg[j].z*ps - mus[tdq+2]) * msc; \
        float f3 = elu_p1(kreg[j].w*ps - mus[tdq+3]) * msc; \
        uint2 kh = { pkh(f0, f1), pkh(f2, f3) }; \
        *(uint2*)&khs[row*PAD + tdq] = kh; \
        uint2 vh = { pkh(vreg[j].x * m, vreg[j].y * m), pkh(vreg[j].z * m, vreg[j].w * m) }; \
        *(uint2*)&vhs[row*PAD + tdq] = vh; \
    } } while (0)

    LOAD_TILE(0);

    for (int tile = 0; tile < NTILE; tile++) {
        __syncthreads();                  // prev MMA done; mus visible on tile 0
        TRANSFORM();
        if (tile + 1 < NTILE) LOAD_TILE(tile + 1);
        __syncthreads();

#pragma unroll
        for (int kl = 0; kl < 64; kl += 16) {
            const uint32_t kadd = (uint32_t)(kl * PAD * 2);
            uint32_t ah[4];
            ldsm4t(skh + kadd + aoff, ah);
            uint32_t bh0[4], bh1[4];
            ldsm4t(svh + kadd + boff,      bh0);
            ldsm4t(svh + kadd + boff + 32, bh1);
            mma16816(acc[0], ah, bh0[0], bh0[1]);
            mma16816(acc[1], ah, bh0[2], bh0[3]);
            mma16816(acc[2], ah, bh1[0], bh1[1]);
            mma16816(acc[3], ah, bh1[2], bh1[3]);
        }
    }
#undef LOAD_TILE
#undef TRANSFORM

    float* outp = g_scratch + ((size_t)chunk*BH + bhidx) * 4096;
    const int rw = lane >> 2, cq = (lane & 3) * 2;
#pragma unroll
    for (int j = 0; j < 4; j++) {
        float2 lo = { acc[j][0], acc[j][1] };
        float2 hi = { acc[j][2], acc[j][3] };
        *(float2*)&outp[(md + rw) * 64 + ne + 8*j + cq]     = lo;
        *(float2*)&outp[(md + 8 + rw) * 64 + ne + 8*j + cq] = hi;
    }
}

// ============================================================
// Reduce: KV = sum over 16 chunks; emit fp16. grid (BH, 4), 256 thr.
// ============================================================
__global__ void __launch_bounds__(256)
reduce_kernel() {
    const int bhidx = blockIdx.x, part = blockIdx.y, t = threadIdx.x;
    const int pos = part*1024 + t*4;
    float4 s = make_float4(0.f, 0.f, 0.f, 0.f);
#pragma unroll
    for (int c = 0; c < NCHUNK; c++) {
        const float4 v = *(const float4*)(g_scratch + ((size_t)c*BH + bhidx)*4096 + pos);
        s.x += v.x; s.y += v.y; s.z += v.z; s.w += v.w;
    }
    uint2 hv = { pkh(s.x, s.y), pkh(s.z, s.w) };
    *(uint2*)(g_KVh + (size_t)bhidx*4096 + pos) = hv;
}

// ============================================================
// Phase 2: out[l][e] = sum_d Qf[l][d]*KV[d][e]  (fp16 single-pass)
// grid (Ll/P2ROWS, BH) = (32, 64), 256 thr / 8 warps.
// Each CTA: KV once, then 4 tiles of 64 Q rows:
//   sync -> TRANSQ(regs) -> LOADQ(t+1) -> sync -> MMA+STG
// ============================================================
__global__ void __launch_bounds__(256)
phase2_kernel(const float* __restrict__ Qp, float* __restrict__ outp) {
    __shared__ __half qhs[64*PAD], kvs[64*PAD];
    const int t = threadIdx.x, lane = t & 31, w = t >> 5;
    const int rb = blockIdx.x, bhidx = blockIdx.y;

    // KV tile once per CTA (L2-resident source)
    {
        const int row = t >> 2, cg = (t & 3) * 16;
        *(uint4*)&kvs[row*PAD + cg]     = *(const uint4*)(g_KVh + (size_t)bhidx*4096 + row*64 + cg);
        *(uint4*)&kvs[row*PAD + cg + 8] = *(const uint4*)(g_KVh + (size_t)bhidx*4096 + row*64 + cg + 8);
    }

    const float* __restrict__ Qb = Qp + ((size_t)bhidx*Ll + (size_t)rb*P2ROWS) * 64;
    float* __restrict__ Ob = outp + ((size_t)bhidx*Ll + (size_t)rb*P2ROWS) * 64;

    const int md = (w & 3) * 16, ne = (w >> 2) * 32;
    const int gr = lane >> 3, r8 = lane & 7;
    const uint32_t aoff = ((uint32_t)((md + ((gr & 1) ? 8 : 0) + r8) * PAD + ((gr & 2) ? 8 : 0))) * 2;
    const uint32_t boff = ((uint32_t)((((gr & 1) ? 8 : 0) + r8) * PAD + ne + ((gr & 2) ? 8 : 0))) * 2;
    const uint32_t sqh = s2u(qhs), svh = s2u(kvs);
    const int rw = lane >> 2, cq = (lane & 3) * 2;

    float4 qreg[4];
    const int trow = t >> 4, tdq = (t & 15) * 4;

#define LOADQ(tl) do { const int _l0 = (tl) * 64; \
    _Pragma("unroll") \
    for (int j = 0; j < 4; j++) { \
        qreg[j] = *(const float4*)(Qb + (size_t)(_l0 + trow + 16*j)*64 + tdq); \
    } } while (0)

#define TRANSQ() do { \
    _Pragma("unroll") \
    for (int j = 0; j < 4; j++) { \
        const int row = trow + 16*j; \
        float f0 = elu_p1(qreg[j].x) * SCALE, f1 = elu_p1(qreg[j].y) * SCALE; \
        float f2 = elu_p1(qreg[j].z) * SCALE, f3 = elu_p1(qreg[j].w) * SCALE; \
        uint2 qh = { pkh(f0, f1), pkh(f2, f3) }; \
        *(uint2*)&qhs[row*PAD + tdq] = qh; \
    } } while (0)

    LOADQ(0);

    for (int tile = 0; tile < P2TILES; tile++) {
        __syncthreads();                  // prev MMA done; KV visible on tile 0
        TRANSQ();
        if (tile + 1 < P2TILES) LOADQ(tile + 1);
        __syncthreads();

        float acc[4][4];
#pragma unroll
        for (int i = 0; i < 4; i++)
#pragma unroll
            for (int j = 0; j < 4; j++) acc[i][j] = 0.f;

#pragma unroll
        for (int kd = 0; kd < 64; kd += 16) {
            uint32_t ah[4];
            ldsm4(sqh + aoff + (uint32_t)(kd*2), ah);
#pragma unroll
            for (int p = 0; p < 2; p++) {
                const uint32_t badd = (uint32_t)(kd * PAD * 2 + p * 32);
                uint32_t vh[4];
                ldsm4t(svh + badd + boff, vh);
                mma16816(acc[2*p],   ah, vh[0], vh[1]);
                mma16816(acc[2*p+1], ah, vh[2], vh[3]);
            }
        }

        float* __restrict__ ob = Ob + (size_t)tile*64*64;
#pragma unroll
        for (int j = 0; j < 4; j++) {
            float2 lo = { acc[j][0], acc[j][1] };
            float2 hi = { acc[j][2], acc[j][3] };
            *(float2*)&ob[(md + rw) * 64 + ne + 8*j + cq]     = lo;
            *(float2*)&ob[(md + 8 + rw) * 64 + ne + 8*j + cq] = hi;
        }
    }
#undef LOADQ
#undef TRANSQ
}

// ============================================================
// Launch
// ============================================================
extern "C" void kernel_launch(void* const* d_in, const int* in_sizes, int n_in,
                              void* d_out, int out_size) {
    const float* Q    = (const float*)d_in[0];
    const float* K    = (const float*)d_in[1];
    const float* V    = (const float*)d_in[2];
    const float* mask = (const float*)d_in[3];
    const float* pi   = (const float*)d_in[4];
    const float* mu   = (const float*)d_in[5];
    float* out = (float*)d_out;

    dim3 g1(NCHUNK, BH);
    phase1_kernel<<<g1, 256>>>(K, V, mask, pi, mu);
    dim3 g2(BH, 4);
    reduce_kernel<<<g2, 256>>>();
    dim3 g3(Ll / P2ROWS, BH);
    phase2_kernel<<<g3, 256>>>(Q, out);
}